// round 6
// baseline (speedup 1.0000x reference)
#include <cuda_runtime.h>
#include <cuda_bf16.h>

// DWTLoss: single-level Haar DWT L1 loss between pred and target.
// [32,3,512,512] fp32 x2 = 201.3 MB streamed once -> HBM-bound.
//
// Per 2x2 block with diffs da,db,dc,dd:
//   sum of 4 normalized subband |.| terms = max(|da+db|,|dc+dd|) + max(|da-db|,|dc-dd|)
// loss = (1/N_BLOCKS) * sum, N_BLOCKS = 32*3*256*256.
//
// R6: single-wave launch. 1024 CTAs x 256 thr = 262,144 threads, ALL resident
// (6-7 CTAs/SM within the 64-warp limit), exactly 12 items/thread. Removes the
// 1.73-wave structure of R5 (2048 CTAs / 1184 resident) that left DRAM at 74%.
// __ldcs evict-first loads: 201 MB read-once through 126 MB L2.

#define N_BLOCKS_HAAR (32 * 3 * 256 * 256)   // 6,291,456
#define N_ITEMS       (32 * 3 * 256 * 128)   // 3,145,728 float4-pair items
#define GRID_CTAS     1024
#define CTA_THREADS   256
#define N_THREADS     (GRID_CTAS * CTA_THREADS)   // 262,144
#define ITEMS_PER_THR (N_ITEMS / N_THREADS)       // exactly 12
#define ROW_F4        128                          // float4 per 512-wide row

__device__ double g_dwt_acc;
__device__ unsigned int g_dwt_count;

__global__ void __launch_bounds__(CTA_THREADS) dwt_loss_fused_kernel(
    const float* __restrict__ pred,
    const float* __restrict__ target,
    float* __restrict__ out)
{
    const float4* __restrict__ p4 = (const float4*)pred;
    const float4* __restrict__ t4 = (const float4*)target;

    const int tid = blockIdx.x * CTA_THREADS + threadIdx.x;

    float acc = 0.0f;
    #pragma unroll 2
    for (int it = 0; it < ITEMS_PER_THR; it++) {
        const int i = tid + it * N_THREADS;
        // item i = (plane, row-pair, col4); float4 index of top row:
        //   base = i + (i & ~127)   (absorbs plane*2 and row-pair*2 doubling)
        const int base = i + (i & ~127);

        float4 p0 = __ldcs(p4 + base);
        float4 p1 = __ldcs(p4 + base + ROW_F4);
        float4 q0 = __ldcs(t4 + base);
        float4 q1 = __ldcs(t4 + base + ROW_F4);

        // block 0 (lanes x,y)
        float da = p0.x - q0.x, db = p0.y - q0.y;
        float dc = p1.x - q1.x, dd = p1.y - q1.y;
        acc += fmaxf(fabsf(da + db), fabsf(dc + dd))
             + fmaxf(fabsf(da - db), fabsf(dc - dd));

        // block 1 (lanes z,w)
        da = p0.z - q0.z; db = p0.w - q0.w;
        dc = p1.z - q1.z; dd = p1.w - q1.w;
        acc += fmaxf(fabsf(da + db), fabsf(dc + dd))
             + fmaxf(fabsf(da - db), fabsf(dc - dd));
    }

    // intra-warp reduce
    #pragma unroll
    for (int o = 16; o > 0; o >>= 1)
        acc += __shfl_xor_sync(0xffffffffu, acc, o);

    __shared__ float sm[CTA_THREADS / 32];
    const int lane = threadIdx.x & 31;
    const int warp = threadIdx.x >> 5;
    if (lane == 0) sm[warp] = acc;
    __syncthreads();

    if (warp == 0) {
        float v = (lane < CTA_THREADS / 32) ? sm[lane] : 0.0f;
        #pragma unroll
        for (int o = 4; o > 0; o >>= 1)
            v += __shfl_xor_sync(0xffffffffu, v, o);

        if (lane == 0) {
            atomicAdd(&g_dwt_acc, (double)v);
            __threadfence();
            unsigned int prev = atomicAdd(&g_dwt_count, 1u);
            if (prev == GRID_CTAS - 1) {
                // last CTA: all g_dwt_acc adds visible (fence + atomic order).
                // Read-and-reset so every graph replay starts from zeroed state.
                unsigned long long raw =
                    atomicExch((unsigned long long*)&g_dwt_acc, 0ull);
                double total = __longlong_as_double((long long)raw);
                out[0] = (float)(total * (1.0 / (double)N_BLOCKS_HAAR));
                atomicExch(&g_dwt_count, 0u);
            }
        }
    }
}

extern "C" void kernel_launch(void* const* d_in, const int* in_sizes, int n_in,
                              void* d_out, int out_size) {
    const float* pred   = (const float*)d_in[0];
    const float* target = (const float*)d_in[1];
    float* out = (float*)d_out;

    dwt_loss_fused_kernel<<<GRID_CTAS, CTA_THREADS>>>(pred, target, out);
}

// round 7
// speedup vs baseline: 1.1024x; 1.1024x over previous
#include <cuda_runtime.h>
#include <cuda_bf16.h>

// DWTLoss: single-level Haar DWT L1 loss between pred and target.
// [32,3,512,512] fp32 x2 = 201.3 MB streamed once -> HBM-bound.
//
// Per 2x2 block with diffs da,db,dc,dd:
//   sum of 4 normalized subband |.| terms = max(|da+db|,|dc+dd|) + max(|da-db|,|dc-dd|)
// loss = (1/N_BLOCKS) * sum, N_BLOCKS = 32*3*256*256.
//
// R7: perfectly balanced single wave. grid = 148 SMs * 8 CTAs = 1184,
// __launch_bounds__(256, 8) forces <=32 regs so all 8 CTAs (64 warps) fit on
// every SM. Grid-stride loop (10-11 items/thread). Plain loads (no __ldcs --
// it cost 2 regs and an occupancy tier in R6).

#define N_BLOCKS_HAAR (32 * 3 * 256 * 256)   // 6,291,456
#define N_ITEMS       (32 * 3 * 256 * 128)   // 3,145,728 float4-pair items
#define GRID_CTAS     1184                    // 148 * 8 -> exactly one full wave
#define CTA_THREADS   256
#define N_THREADS     (GRID_CTAS * CTA_THREADS)   // 303,104
#define ROW_F4        128                          // float4 per 512-wide row

__device__ double g_dwt_acc;
__device__ unsigned int g_dwt_count;

__global__ void __launch_bounds__(CTA_THREADS, 8) dwt_loss_fused_kernel(
    const float* __restrict__ pred,
    const float* __restrict__ target,
    float* __restrict__ out)
{
    const float4* __restrict__ p4 = (const float4*)pred;
    const float4* __restrict__ t4 = (const float4*)target;

    const int tid = blockIdx.x * CTA_THREADS + threadIdx.x;

    float acc = 0.0f;
    #pragma unroll 2
    for (int i = tid; i < N_ITEMS; i += N_THREADS) {
        // item i = (plane, row-pair, col4); float4 index of top row:
        //   base = i + (i & ~127)   (absorbs plane*2 and row-pair*2 doubling)
        const int base = i + (i & ~127);

        float4 p0 = p4[base];
        float4 p1 = p4[base + ROW_F4];
        float4 q0 = t4[base];
        float4 q1 = t4[base + ROW_F4];

        // block 0 (lanes x,y)
        float da = p0.x - q0.x, db = p0.y - q0.y;
        float dc = p1.x - q1.x, dd = p1.y - q1.y;
        acc += fmaxf(fabsf(da + db), fabsf(dc + dd))
             + fmaxf(fabsf(da - db), fabsf(dc - dd));

        // block 1 (lanes z,w)
        da = p0.z - q0.z; db = p0.w - q0.w;
        dc = p1.z - q1.z; dd = p1.w - q1.w;
        acc += fmaxf(fabsf(da + db), fabsf(dc + dd))
             + fmaxf(fabsf(da - db), fabsf(dc - dd));
    }

    // intra-warp reduce
    #pragma unroll
    for (int o = 16; o > 0; o >>= 1)
        acc += __shfl_xor_sync(0xffffffffu, acc, o);

    __shared__ float sm[CTA_THREADS / 32];
    const int lane = threadIdx.x & 31;
    const int warp = threadIdx.x >> 5;
    if (lane == 0) sm[warp] = acc;
    __syncthreads();

    if (warp == 0) {
        float v = (lane < CTA_THREADS / 32) ? sm[lane] : 0.0f;
        #pragma unroll
        for (int o = 4; o > 0; o >>= 1)
            v += __shfl_xor_sync(0xffffffffu, v, o);

        if (lane == 0) {
            atomicAdd(&g_dwt_acc, (double)v);
            __threadfence();
            unsigned int prev = atomicAdd(&g_dwt_count, 1u);
            if (prev == GRID_CTAS - 1) {
                // last CTA: all g_dwt_acc adds visible (fence + atomic order).
                // Read-and-reset so every graph replay starts from zeroed state.
                unsigned long long raw =
                    atomicExch((unsigned long long*)&g_dwt_acc, 0ull);
                double total = __longlong_as_double((long long)raw);
                out[0] = (float)(total * (1.0 / (double)N_BLOCKS_HAAR));
                atomicExch(&g_dwt_count, 0u);
            }
        }
    }
}

extern "C" void kernel_launch(void* const* d_in, const int* in_sizes, int n_in,
                              void* d_out, int out_size) {
    const float* pred   = (const float*)d_in[0];
    const float* target = (const float*)d_in[1];
    float* out = (float*)d_out;

    dwt_loss_fused_kernel<<<GRID_CTAS, CTA_THREADS>>>(pred, target, out);
}

// round 8
// speedup vs baseline: 1.1668x; 1.0585x over previous
#include <cuda_runtime.h>
#include <cuda_bf16.h>

// DWTLoss: single-level Haar DWT L1 loss between pred and target.
// [32,3,512,512] fp32 x2 = 201.3 MB streamed once -> HBM-bound.
//
// Per 2x2 block with diffs da,db,dc,dd:
//   sum of 4 normalized subband |.| terms = max(|da+db|,|dc+dd|) + max(|da-db|,|dc-dd|)
// loss = (1/N_BLOCKS) * sum, N_BLOCKS = 32*3*256*256.
//
// R8: exact two-phase partition to kill the grid-stride tail.
//  - main: exactly 10 float4-pair items per thread, no bounds check
//  - remainder: 114,688 items re-expressed as 229,376 2x2-block units
//    (float2 granularity, 32B/unit); 76% of threads do exactly one, no loop.
// Launch: 148 SMs * 8 CTAs = 1184 x 256 thr, __launch_bounds__(256,8) -> <=32 regs,
// one perfectly full wave.

#define N_BLOCKS_HAAR (32 * 3 * 256 * 256)   // 6,291,456
#define N_ITEMS       (32 * 3 * 256 * 128)   // 3,145,728 float4-pair items
#define GRID_CTAS     1184                    // 148 * 8 -> exactly one full wave
#define CTA_THREADS   256
#define N_THREADS     (GRID_CTAS * CTA_THREADS)   // 303,104
#define MAIN_IPT      10                           // uniform items per thread
#define MAIN_ITEMS    (N_THREADS * MAIN_IPT)       // 3,031,040
#define REM_BLOCKS    ((N_ITEMS - MAIN_ITEMS) * 2) // 229,376 2x2-block units
#define ROW_F4        128                          // float4 per 512-wide row
#define ROW_F2        256                          // float2 per 512-wide row

__device__ double g_dwt_acc;
__device__ unsigned int g_dwt_count;

__global__ void __launch_bounds__(CTA_THREADS, 8) dwt_loss_fused_kernel(
    const float* __restrict__ pred,
    const float* __restrict__ target,
    float* __restrict__ out)
{
    const float4* __restrict__ p4 = (const float4*)pred;
    const float4* __restrict__ t4 = (const float4*)target;

    const int tid = blockIdx.x * CTA_THREADS + threadIdx.x;

    float acc = 0.0f;

    // ---- phase 1: exactly 10 items per thread, fully uniform ----
    #pragma unroll 2
    for (int it = 0; it < MAIN_IPT; it++) {
        const int i = tid + it * N_THREADS;
        // item i = (plane, row-pair, col4); float4 index of top row:
        //   base = i + (i & ~127)   (absorbs plane*2 and row-pair*2 doubling)
        const int base = i + (i & ~127);

        float4 p0 = p4[base];
        float4 p1 = p4[base + ROW_F4];
        float4 q0 = t4[base];
        float4 q1 = t4[base + ROW_F4];

        // block 0 (lanes x,y)
        float da = p0.x - q0.x, db = p0.y - q0.y;
        float dc = p1.x - q1.x, dd = p1.y - q1.y;
        acc += fmaxf(fabsf(da + db), fabsf(dc + dd))
             + fmaxf(fabsf(da - db), fabsf(dc - dd));

        // block 1 (lanes z,w)
        da = p0.z - q0.z; db = p0.w - q0.w;
        dc = p1.z - q1.z; dd = p1.w - q1.w;
        acc += fmaxf(fabsf(da + db), fabsf(dc + dd))
             + fmaxf(fabsf(da - db), fabsf(dc - dd));
    }

    // ---- phase 2: remainder at 2x2-block (float2) granularity ----
    // REM_BLOCKS (229,376) < N_THREADS (303,104): at most one unit per thread.
    if (tid < REM_BLOCKS) {
        const float2* __restrict__ p2 = (const float2*)pred;
        const float2* __restrict__ t2 = (const float2*)target;

        const int item = MAIN_ITEMS + (tid >> 1);   // which float4-pair item
        const int half = tid & 1;                   // which 2x2 block inside it
        const int base4 = item + (item & ~127);
        const int f2r0 = 2 * base4 + half;          // float2 index, top row

        float2 p0 = p2[f2r0];
        float2 p1 = p2[f2r0 + ROW_F2];
        float2 q0 = t2[f2r0];
        float2 q1 = t2[f2r0 + ROW_F2];

        float da = p0.x - q0.x, db = p0.y - q0.y;
        float dc = p1.x - q1.x, dd = p1.y - q1.y;
        acc += fmaxf(fabsf(da + db), fabsf(dc + dd))
             + fmaxf(fabsf(da - db), fabsf(dc - dd));
    }

    // intra-warp reduce
    #pragma unroll
    for (int o = 16; o > 0; o >>= 1)
        acc += __shfl_xor_sync(0xffffffffu, acc, o);

    __shared__ float sm[CTA_THREADS / 32];
    const int lane = threadIdx.x & 31;
    const int warp = threadIdx.x >> 5;
    if (lane == 0) sm[warp] = acc;
    __syncthreads();

    if (warp == 0) {
        float v = (lane < CTA_THREADS / 32) ? sm[lane] : 0.0f;
        #pragma unroll
        for (int o = 4; o > 0; o >>= 1)
            v += __shfl_xor_sync(0xffffffffu, v, o);

        if (lane == 0) {
            atomicAdd(&g_dwt_acc, (double)v);
            __threadfence();
            unsigned int prev = atomicAdd(&g_dwt_count, 1u);
            if (prev == GRID_CTAS - 1) {
                // last CTA: all g_dwt_acc adds visible (fence + atomic order).
                // Read-and-reset so every graph replay starts from zeroed state.
                unsigned long long raw =
                    atomicExch((unsigned long long*)&g_dwt_acc, 0ull);
                double total = __longlong_as_double((long long)raw);
                out[0] = (float)(total * (1.0 / (double)N_BLOCKS_HAAR));
                atomicExch(&g_dwt_count, 0u);
            }
        }
    }
}

extern "C" void kernel_launch(void* const* d_in, const int* in_sizes, int n_in,
                              void* d_out, int out_size) {
    const float* pred   = (const float*)d_in[0];
    const float* target = (const float*)d_in[1];
    float* out = (float*)d_out;

    dwt_loss_fused_kernel<<<GRID_CTAS, CTA_THREADS>>>(pred, target, out);
}